// round 12
// baseline (speedup 1.0000x reference)
#include <cuda_runtime.h>
#include <cstdint>

// out[N,N] = diag(ics_mask - params * r_mask), N = 12288. Pure store-bound (604 MB).
// Converged at the chip fill ceiling: 604 MB / ~80.7 us = 7.48 TB/s (93.6% of HBM
// spec), identical across STG.128 / __stcs / driver-memset paths (LTS cap,
// path-independent). Config: 256 thr x 4 block-strided float4 chunks (fully
// coalesced), __stcs evict-first, exact grid.
// R11 refinement: each block covers 4096 elements < N+1 = 12289, so at most ONE
// diagonal element per block -> one div per block instead of one per chunk.

static constexpr unsigned N  = 12288u;
static constexpr unsigned N4 = (N * N) / 4u;   // 37,748,736 float4 stores

__global__ void __launch_bounds__(256) diag_fill_kernel(
    float4* __restrict__ out4,
    const float* __restrict__ params,
    const int*   __restrict__ r_mask,
    const int*   __restrict__ ics_mask)
{
    // Block owns 1024 consecutive float4s = 4096 elements [jb, jb+4096).
    unsigned jb = blockIdx.x * 4096u;

    // At most one diagonal element d = i*(N+1) in this block's range.
    unsigned i = (jb + N) / (N + 1u);          // ceil(jb/(N+1)) -> mul+shift
    unsigned d = i * (N + 1u);                 // may be >= jb+4096 (no hit)
    float diagval = 0.0f;
    if (i < N && d < jb + 4096u)
        diagval = (float)ics_mask[i] - params[i] * (float)r_mask[i];

    unsigned base = blockIdx.x * 1024u + threadIdx.x;

    #pragma unroll
    for (unsigned c = 0; c < 4u; ++c) {
        unsigned f = base + c * 256u;          // float4 index, < N4 exactly
        unsigned j = f * 4u;                   // window [j, j+4)

        float4 v = make_float4(0.f, 0.f, 0.f, 0.f);
        unsigned off = d - j;                  // unsigned: wraps if d < j
        if (off < 4u) {
            if      (off == 0u) v.x = diagval;
            else if (off == 1u) v.y = diagval;
            else if (off == 2u) v.z = diagval;
            else                v.w = diagval;
        }

        __stcs(out4 + f, v);                   // st.global.cs.v4, coalesced
    }
}

extern "C" void kernel_launch(void* const* d_in, const int* in_sizes, int n_in,
                              void* d_out, int out_size)
{
    const float* params   = (const float*)d_in[0];
    const int*   r_mask   = (const int*)  d_in[1];
    const int*   ics_mask = (const int*)  d_in[2];
    float4*      out4     = (float4*)d_out;

    (void)in_sizes; (void)n_in; (void)out_size;

    const unsigned threads = 256;
    const unsigned blocks  = N4 / (threads * 4u);   // 36,864 — exact, no tail
    diag_fill_kernel<<<blocks, threads>>>(out4, params, r_mask, ics_mask);
}

// round 13
// speedup vs baseline: 1.0050x; 1.0050x over previous
#include <cuda_runtime.h>
#include <cstdint>

// out[N,N] = diag(ics_mask - params * r_mask), N = 12288. Pure store-bound (604 MB).
// Converged at chip fill ceiling (~7.45 TB/s true rate, LTS cap, path-independent
// across plain STG / __stcs / driver memset). R12: last untested store path —
// __stwt (st.global.wt, write-through). Hypothesis: avoids the L2 fill-then-drain
// hop for the final-wave lines (~60 MB observed resident in L2 at retire).
// Base-case prediction: neutral; revert to __stcs variant if it regresses.

static constexpr unsigned N  = 12288u;
static constexpr unsigned N4 = (N * N) / 4u;   // 37,748,736 float4 stores

__global__ void __launch_bounds__(256) diag_fill_kernel(
    float4* __restrict__ out4,
    const float* __restrict__ params,
    const int*   __restrict__ r_mask,
    const int*   __restrict__ ics_mask)
{
    // Block owns 1024 consecutive float4s = 4096 elements [jb, jb+4096).
    unsigned jb = blockIdx.x * 4096u;

    // At most one diagonal element d = i*(N+1) per block (4096 < N+1 = 12289).
    unsigned i = (jb + N) / (N + 1u);          // ceil(jb/(N+1)) -> mul+shift
    unsigned d = i * (N + 1u);
    float diagval = 0.0f;
    if (i < N && d < jb + 4096u)
        diagval = (float)ics_mask[i] - params[i] * (float)r_mask[i];

    unsigned base = blockIdx.x * 1024u + threadIdx.x;

    #pragma unroll
    for (unsigned c = 0; c < 4u; ++c) {
        unsigned f = base + c * 256u;          // float4 index, < N4 exactly
        unsigned j = f * 4u;                   // window [j, j+4)

        float4 v = make_float4(0.f, 0.f, 0.f, 0.f);
        unsigned off = d - j;                  // unsigned wrap if d < j
        if (off < 4u) {
            if      (off == 0u) v.x = diagval;
            else if (off == 1u) v.y = diagval;
            else if (off == 2u) v.z = diagval;
            else                v.w = diagval;
        }

        __stwt(out4 + f, v);                   // st.global.wt.v4, coalesced
    }
}

extern "C" void kernel_launch(void* const* d_in, const int* in_sizes, int n_in,
                              void* d_out, int out_size)
{
    const float* params   = (const float*)d_in[0];
    const int*   r_mask   = (const int*)  d_in[1];
    const int*   ics_mask = (const int*)  d_in[2];
    float4*      out4     = (float4*)d_out;

    (void)in_sizes; (void)n_in; (void)out_size;

    const unsigned threads = 256;
    const unsigned blocks  = N4 / (threads * 4u);   // 36,864 — exact, no tail
    diag_fill_kernel<<<blocks, threads>>>(out4, params, r_mask, ics_mask);
}